// round 1
// baseline (speedup 1.0000x reference)
#include <cuda_runtime.h>

// ---------------- problem constants ----------------
#define UDIM   1024      // UNITS == IN_DIM
#define BATCH  32
#define TLEN   2048
#define NROWS  (BATCH * TLEN)   // 65536

// ---------------- scratch (static device globals; no allocation) ----------------
__device__ float g_S0[(size_t)NROWS * UDIM];          // 256 MB: base level / ping
__device__ float g_S1[(size_t)(NROWS / 2) * UDIM];    // 128 MB: pong
__device__ float g_Wb[UDIM * UDIM];                   // W^T  (B-operand format)
__device__ float g_Qa[2][UDIM * UDIM];                // R^(2^r), row-major (A side)
__device__ float g_Qb[2][UDIM * UDIM];                // R^(2^r) transposed (B side)

__device__ __forceinline__ float* bufp(int id) {
    switch (id) {
        case 0: return g_S0;
        case 1: return g_S1;
        case 2: return g_Wb;
        case 3: return g_Qa[0];
        case 4: return g_Qa[1];
        case 5: return g_Qb[0];
        case 6: return g_Qb[1];
    }
    return nullptr;
}

// ---------------- prep: W^T, Q0 = R (both formats) ----------------
__global__ void prep_k(const float* __restrict__ W, const float* __restrict__ R) {
    int idx = blockIdx.x * 256 + threadIdx.x;     // 1M threads
    int r = idx >> 10, c = idx & 1023;
    g_Wb[(size_t)c * UDIM + r] = W[idx];          // Wb[n][k] = W[k][n]
    float rr = R[idx];
    g_Qa[0][idx] = rr;                            // Qa[m][k] = R[m][k]
    g_Qb[0][(size_t)c * UDIM + r] = rr;           // Qb[n][k] = R[k][n]
}

// ---------------- h0 contribution: S0[t=0 rows] += h0 @ R ----------------
__global__ void h0r_k(const float* __restrict__ h0, const float* __restrict__ R) {
    int u = blockIdx.x * 256 + threadIdx.x;       // grid (4, 32)
    int b = blockIdx.y;
    float s = 0.f;
    for (int k = 0; k < UDIM; k++)
        s += h0[b * UDIM + k] * R[(size_t)k * UDIM + u];
    g_S0[(size_t)b * UDIM + u] += s;              // seg t=0, batch b -> row b
}

// ---------------- generic tiled fp32 GEMM ----------------
// C[m][n] = sum_k Aop[m][k] * Bop[n][k]   (both operands K-major, N=K=1024)
// amap:  0 identity | 1 combine-even: src row = m + (m & ~31)
// Add:   if present, adds Add[m + (m & ~31) + 32][n]   (combine-odd rows)
// omode: 0 Out[m][n] | 1 xin remap Out[(m%T)*B + m/T][n] | 2 dual: Out[m][n] & Out2[n][m]
#define BM 128
#define BN 128
#define BK 16
#define PAD 1

__global__ __launch_bounds__(256, 2)
void gemm_k(const float* __restrict__ extA, float* __restrict__ extOut,
            int aid, int bid, int addid, int oid, int o2id,
            int M, int amap, int omode)
{
    const float* A   = (aid == -1) ? extA : bufp(aid);
    const float* Bm  = bufp(bid);
    const float* Add = (addid < 0) ? nullptr : bufp(addid);
    float* Out       = (oid == -1) ? extOut : bufp(oid);
    float* Out2      = (o2id < 0) ? nullptr : bufp(o2id);

    __shared__ float As[BM][BK + PAD];
    __shared__ float Bs[BN][BK + PAD];

    const int tid = threadIdx.x;
    const int tx = tid & 15;
    const int ty = tid >> 4;
    const int m0 = blockIdx.y * BM;
    const int n0 = blockIdx.x * BN;

    float acc[8][8];
    #pragma unroll
    for (int i = 0; i < 8; i++)
        #pragma unroll
        for (int j = 0; j < 8; j++) acc[i][j] = 0.f;

    for (int k0 = 0; k0 < UDIM; k0 += BK) {
        // load tiles: 512 float4 per operand, 2 per thread
        #pragma unroll
        for (int s = tid; s < (BM * BK) / 4; s += 256) {
            int row = s >> 2;
            int c4  = (s & 3) << 2;
            int mrow = m0 + row;
            float4 v = make_float4(0.f, 0.f, 0.f, 0.f);
            if (mrow < M) {
                int ar = amap ? (mrow + (mrow & ~31)) : mrow;
                v = *reinterpret_cast<const float4*>(A + (size_t)ar * UDIM + k0 + c4);
            }
            As[row][c4 + 0] = v.x; As[row][c4 + 1] = v.y;
            As[row][c4 + 2] = v.z; As[row][c4 + 3] = v.w;

            int nrow = n0 + row;
            float4 w = *reinterpret_cast<const float4*>(Bm + (size_t)nrow * UDIM + k0 + c4);
            Bs[row][c4 + 0] = w.x; Bs[row][c4 + 1] = w.y;
            Bs[row][c4 + 2] = w.z; Bs[row][c4 + 3] = w.w;
        }
        __syncthreads();

        #pragma unroll
        for (int kk = 0; kk < BK; kk++) {
            float a[8], b[8];
            #pragma unroll
            for (int i = 0; i < 8; i++) a[i] = As[i * 16 + ty][kk];
            #pragma unroll
            for (int j = 0; j < 8; j++) b[j] = Bs[j * 16 + tx][kk];
            #pragma unroll
            for (int i = 0; i < 8; i++)
                #pragma unroll
                for (int j = 0; j < 8; j++) acc[i][j] += a[i] * b[j];
        }
        __syncthreads();
    }

    // epilogue
    #pragma unroll
    for (int i = 0; i < 8; i++) {
        int m = m0 + i * 16 + ty;
        if (m >= M) continue;
        #pragma unroll
        for (int j = 0; j < 8; j++) {
            int n = n0 + j * 16 + tx;
            float v = acc[i][j];
            if (Add) v += Add[(size_t)(m + (m & ~31) + 32) * UDIM + n];
            if (omode == 0) {
                Out[(size_t)m * UDIM + n] = v;
            } else if (omode == 1) {
                int orow = (m & (TLEN - 1)) * BATCH + (m >> 11);
                Out[(size_t)orow * UDIM + n] = v;
            } else {
                Out[(size_t)m * UDIM + n] = v;
                Out2[(size_t)n * UDIM + m] = v;
            }
        }
    }
}

// ---------------- launch ----------------
extern "C" void kernel_launch(void* const* d_in, const int* in_sizes, int n_in,
                              void* d_out, int out_size)
{
    const float* x  = (const float*)d_in[0];   // [B, T, IN]
    const float* h0 = (const float*)d_in[1];   // [B, U]  (zeros)
    const float* W  = (const float*)d_in[2];   // [IN, U]
    const float* R  = (const float*)d_in[3];   // [U, U]
    float* out = (float*)d_out;                // [B, U]

    (void)in_sizes; (void)n_in; (void)out_size;

    // operand prep
    prep_k<<<4096, 256>>>(W, R);

    // base level: S0[t*32+b] = x[b,t,:] @ W   (omode 1 does the (b,t)->(t,b) remap)
    gemm_k<<<dim3(8, NROWS / BM), 256>>>(x, nullptr, -1, 2, -2, 0, -2, NROWS, 0, 1);

    // fold h0: S0[t=0 rows] += h0 @ R
    h0r_k<<<dim3(4, BATCH), 256>>>(h0, R);

    // reduction tree: 11 rounds. Round r: combine pairs with Q = R^(2^r),
    // and (for r < 10) square Q for the next round.
    int aid = 0, oid = 1, q = 0;
    for (int r = 0; r < 11; r++) {
        int Mout = NROWS >> (r + 1);
        int ooid = (r == 10) ? -1 : oid;
        gemm_k<<<dim3(8, (Mout + BM - 1) / BM), 256>>>(
            nullptr, out, aid, 5 + q, aid, ooid, -2, Mout, 1, 0);
        if (r < 10)
            gemm_k<<<dim3(8, 8), 256>>>(
                nullptr, nullptr, 3 + q, 5 + q, -2, 3 + (q ^ 1), 5 + (q ^ 1),
                UDIM, 0, 2);
        int t = aid; aid = oid; oid = t;
        q ^= 1;
    }
}